// round 15
// baseline (speedup 1.0000x reference)
#include <cuda_runtime.h>

// Problem constants: B=8, C=64, H=W=48, N=2304
#define BB 8
#define CC 64
#define NN 2304
#define KS 66   // smem row stride (floats): 64 data + 2 pad, stride%4==2 -> conflict-free LDS.64

// Scratch (allocation-free rule: __device__ globals)
__device__ float g_qT[(size_t)BB * NN * CC];   // q transposed: [b][n][c], 4.7 MB
__device__ float g_rowsum[BB * NN];            // softmax row sums

// ---- packed fp32x2 helpers (FFMA2) ----
__device__ __forceinline__ void fma2(unsigned long long &d, unsigned long long a, unsigned long long b) {
    asm("fma.rn.f32x2 %0, %1, %2, %0;" : "+l"(d) : "l"(a), "l"(b));
}
__device__ __forceinline__ float2 unpk(unsigned long long p) {
    float2 r; asm("mov.b64 {%0,%1}, %2;" : "=f"(r.x), "=f"(r.y) : "l"(p)); return r;
}

// ============================================================
// K1: q = l2normalize(x + gamma*pos, axis=C), stored as [b][n][c].
//     Also zeroes g_rowsum (one entry per (b,n) -- same thread count).
// ============================================================
__global__ void k_q(const float* __restrict__ x, const float* __restrict__ pos,
                    const float* __restrict__ gp) {
    int idx = blockIdx.x * blockDim.x + threadIdx.x;   // 0 .. B*N-1 exactly
    g_rowsum[idx] = 0.0f;
    int b = idx / NN, n = idx % NN;
    float gamma = *gp;
    const float* xb = x   + (size_t)b * CC * NN + n;
    const float* pb = pos + (size_t)b * CC * NN + n;
    float vals[CC];
    float ss = 1e-6f;   // EPS inside the sqrt, matches reference
#pragma unroll
    for (int c = 0; c < CC; c++) {
        float t = __fmaf_rn(gamma, pb[(size_t)c * NN], xb[(size_t)c * NN]);
        vals[c] = t;
        ss = __fmaf_rn(t, t, ss);
    }
    float r = rsqrtf(ss);
    float* qb = g_qT + ((size_t)b * NN + n) * CC;
#pragma unroll
    for (int c = 0; c < CC; c++) qb[c] = vals[c] * r;
}

// ============================================================
// K2: Gram GEMM tile (128x128, K=C=64) + fused exp + row-sum atomics.
//     Writes unnormalized E = exp(beta_gamma * <q_n, q_m>) into beta region.
//     |score| <= beta_gamma (q unit vectors) so no max-subtraction needed.
//     256 threads, 8x8 micro-tile, FFMA2 paired along K.
// ============================================================
__global__ void __launch_bounds__(256, 1)
k_gram(const float* __restrict__ bgp, float* __restrict__ beta) {
    extern __shared__ float sh[];
    float* As = sh;              // [128][KS]
    float* Bs = sh + 128 * KS;   // [128][KS]

    int b  = blockIdx.z;
    int n0 = blockIdx.x * 128;
    int m0 = blockIdx.y * 128;
    int t  = threadIdx.x;

    const float* qb = g_qT + (size_t)b * NN * CC;
#pragma unroll
    for (int r = 0; r < 16; r++) {
        int idx = t + 256 * r;        // 0..4095 = 128 rows x 32 float2
        int row = idx >> 5;
        int kp  = (idx & 31) << 1;
        *(float2*)(As + row * KS + kp) = *(const float2*)(qb + (size_t)(n0 + row) * CC + kp);
        *(float2*)(Bs + row * KS + kp) = *(const float2*)(qb + (size_t)(m0 + row) * CC + kp);
    }
    __syncthreads();

    int ty = t >> 4, tx = t & 15;
    const float* Ab = As + ty * 8 * KS;   // 8 blocked rows (broadcast loads)
    const float* Bb = Bs + tx * KS;       // 8 interleaved cols: j = tx + 16*jj

    unsigned long long acc[8][8];
#pragma unroll
    for (int i = 0; i < 8; i++)
#pragma unroll
        for (int j = 0; j < 8; j++) acc[i][j] = 0ull;

#pragma unroll 4
    for (int kk = 0; kk < CC; kk += 2) {
        unsigned long long aa[8];
#pragma unroll
        for (int i = 0; i < 8; i++)
            aa[i] = *(const unsigned long long*)(Ab + i * KS + kk);
#pragma unroll
        for (int jj = 0; jj < 8; jj++) {
            unsigned long long bb = *(const unsigned long long*)(Bb + jj * 16 * KS + kk);
#pragma unroll
            for (int i = 0; i < 8; i++) fma2(acc[i][jj], aa[i], bb);
        }
    }

    float bg = *bgp;
#pragma unroll
    for (int i = 0; i < 8; i++) {
        float* bp = beta + ((size_t)b * NN + n0 + ty * 8 + i) * NN + m0 + tx;
        float rs = 0.0f;
#pragma unroll
        for (int jj = 0; jj < 8; jj++) {
            float2 p = unpk(acc[i][jj]);
            float e = __expf((p.x + p.y) * bg);
            bp[jj * 16] = e;
            rs += e;
        }
        // reduce rs across the 16 tx lanes (contiguous half-warp group)
        rs += __shfl_down_sync(0xffffffffu, rs, 8);
        rs += __shfl_down_sync(0xffffffffu, rs, 4);
        rs += __shfl_down_sync(0xffffffffu, rs, 2);
        rs += __shfl_down_sync(0xffffffffu, rs, 1);
        if (tx == 0) atomicAdd(&g_rowsum[b * NN + n0 + ty * 8 + i], rs);
    }
}

// ============================================================
// K3: in-place softmax normalization of beta: one block per row.
// ============================================================
__global__ void k_norm(float* __restrict__ beta) {
    int row = blockIdx.x;                  // 0 .. B*N-1
    float inv = 1.0f / g_rowsum[row];
    float4* p = (float4*)(beta + (size_t)row * NN);
    for (int i = threadIdx.x; i < NN / 4; i += blockDim.x) {
        float4 w = p[i];
        w.x *= inv; w.y *= inv; w.z *= inv; w.w *= inv;
        p[i] = w;
    }
}

// ============================================================
// K4: O = V * beta^T (per batch, [64 c] x [128 n] tile, K=N over 64-chunks)
//     + fused final blend out = w0*o + w1*v.
//     256 threads, 4x8 micro-tile, FFMA2 paired along K(m).
// ============================================================
__global__ void __launch_bounds__(256, 1)
k_o(const float* __restrict__ v, const float* __restrict__ beta,
    const float* __restrict__ sg0, const float* __restrict__ sg1,
    float* __restrict__ out) {
    extern __shared__ float sh[];
    float* Vs = sh;             // [64][KS]
    float* Es = sh + 64 * KS;   // [128][KS]

    int b  = blockIdx.y;
    int n0 = blockIdx.x * 128;
    int t  = threadIdx.x;
    int ty = t >> 4, tx = t & 15;

    unsigned long long acc[4][8];
#pragma unroll
    for (int i = 0; i < 4; i++)
#pragma unroll
        for (int j = 0; j < 8; j++) acc[i][j] = 0ull;

    const float* vb = v + (size_t)b * CC * NN;
    const float* eb = beta + ((size_t)b * NN + n0) * NN;

    for (int mt = 0; mt < NN; mt += 64) {
#pragma unroll
        for (int r = 0; r < 8; r++) {                  // Vs: 64 rows x 32 float2
            int idx = t + 256 * r;
            int row = idx >> 5;
            int kp  = (idx & 31) << 1;
            *(float2*)(Vs + row * KS + kp) = *(const float2*)(vb + (size_t)row * NN + mt + kp);
        }
#pragma unroll
        for (int r = 0; r < 16; r++) {                 // Es: 128 rows x 32 float2
            int idx = t + 256 * r;
            int row = idx >> 5;
            int kp  = (idx & 31) << 1;
            *(float2*)(Es + row * KS + kp) = *(const float2*)(eb + (size_t)row * NN + mt + kp);
        }
        __syncthreads();

        const float* Ab = Vs + ty * 4 * KS;
        const float* Bb = Es + tx * KS;
#pragma unroll 4
        for (int kk = 0; kk < 64; kk += 2) {
            unsigned long long aa[4];
#pragma unroll
            for (int i = 0; i < 4; i++)
                aa[i] = *(const unsigned long long*)(Ab + i * KS + kk);
#pragma unroll
            for (int jj = 0; jj < 8; jj++) {
                unsigned long long bb = *(const unsigned long long*)(Bb + jj * 16 * KS + kk);
#pragma unroll
                for (int i = 0; i < 4; i++) fma2(acc[i][jj], aa[i], bb);
            }
        }
        __syncthreads();   // protect smem before next tile overwrite
    }

    float e0 = __expf(*sg0), e1 = __expf(*sg1);
    float w0 = e0 / (e0 + e1), w1 = e1 / (e0 + e1);
#pragma unroll
    for (int i = 0; i < 4; i++) {
#pragma unroll
        for (int jj = 0; jj < 8; jj++) {
            float2 p = unpk(acc[i][jj]);
            float o = p.x + p.y;
            size_t off = ((size_t)b * CC + ty * 4 + i) * NN + n0 + tx + 16 * jj;
            out[off] = w0 * o + w1 * v[off];
        }
    }
}

// ============================================================

#define GRAM_SMEM (2 * 128 * KS * sizeof(float))        // 67584 B
#define O_SMEM    ((64 + 128) * KS * sizeof(float))     // 50688 B

extern "C" void kernel_launch(void* const* d_in, const int* in_sizes, int n_in,
                              void* d_out, int out_size) {
    const float* x   = (const float*)d_in[0];
    const float* v   = (const float*)d_in[1];
    const float* pos = (const float*)d_in[2];
    const float* gma = (const float*)d_in[3];
    const float* bg  = (const float*)d_in[4];
    const float* sg0 = (const float*)d_in[5];
    const float* sg1 = (const float*)d_in[6];

    float* out  = (float*)d_out;                          // [B, C, H, W]
    float* beta = out + (size_t)BB * CC * NN;             // [B, N, N]

    cudaFuncSetAttribute(k_gram, cudaFuncAttributeMaxDynamicSharedMemorySize, (int)GRAM_SMEM);
    cudaFuncSetAttribute(k_o,    cudaFuncAttributeMaxDynamicSharedMemorySize, (int)O_SMEM);

    // K1: q + zero rowsums
    k_q<<<(BB * NN) / 256, 256>>>(x, pos, gma);

    // K2: Gram + exp + rowsum
    dim3 g2(NN / 128, NN / 128, BB);                      // (18, 18, 8)
    k_gram<<<g2, 256, GRAM_SMEM>>>(bg, beta);

    // K3: normalize beta in place
    k_norm<<<BB * NN, 256>>>(beta);

    // K4: O = V * beta^T, blended output
    dim3 g4(NN / 128, BB);                                // (18, 8)
    k_o<<<g4, 256, O_SMEM>>>(v, beta, sg0, sg1, out);
}